// round 1
// baseline (speedup 1.0000x reference)
#include <cuda_runtime.h>
#include <cuda_bf16.h>
#include <math.h>

// ---------------- problem constants ----------------
// B=8, C=2, H=256, W=64, PH=PW=4, HP=64, WP=16, N=1024, HID=1024,
// NH=16, HD=64, DEPTH=8, FFN=2730, TDIM=256, OUT=32
constexpr int   kFFN  = 2730;
constexpr float kEPS  = 1e-6f;

// ---------------- device scratch (single symbol, ~1.0 GB) ----------------
constexpr size_t SZ_TEMB = 8ULL * 256;
constexpr size_t SZ_CS   = 8ULL * 1024;
constexpr size_t SZ_ADA  = 8ULL * 6144;
constexpr size_t SZ_FADA = 8ULL * 2048;
constexpr size_t SZ_H    = 8192ULL * 1024;
constexpr size_t SZ_QKV  = 8192ULL * 3072;
constexpr size_t SZ_X12  = 8192ULL * 5460;
constexpr size_t SZ_G    = 8192ULL * 2730;
constexpr size_t SZ_Y    = 8192ULL * 32;
constexpr size_t SZ_SC   = 128ULL * 1024 * 1024;

constexpr size_t OFF_TEMB = 0;
constexpr size_t OFF_CS   = OFF_TEMB + SZ_TEMB;
constexpr size_t OFF_ADA  = OFF_CS   + SZ_CS;
constexpr size_t OFF_FADA = OFF_ADA  + SZ_ADA;
constexpr size_t OFF_H    = OFF_FADA + SZ_FADA;
constexpr size_t OFF_HN   = OFF_H    + SZ_H;
constexpr size_t OFF_QKV  = OFF_HN   + SZ_H;
constexpr size_t OFF_O    = OFF_QKV  + SZ_QKV;
constexpr size_t OFF_X12  = OFF_O    + SZ_H;
constexpr size_t OFF_G    = OFF_X12  + SZ_X12;
constexpr size_t OFF_Y    = OFF_G    + SZ_G;
constexpr size_t OFF_SC   = OFF_Y    + SZ_Y;
constexpr size_t SCRATCH_TOTAL = OFF_SC + SZ_SC;

__device__ float g_scratch[SCRATCH_TOTAL];

// ---------------- generic batched GEMM ----------------
// C[m,n] = act( sum_k A[m,k] * W[n,k] + bias[n] )                (gate==nullptr)
// C[m,n] += gate[(m>>10)*gateStride + n] * (sum_k ... + bias[n]) (gate!=nullptr)
// A addr:  A + m*lda + k
// W addr:  W + n*ldbn + k*ldbk
// batch z: base += (z/zdiv)*s1 + (z%zdiv)*s2   (per-operand)
__global__ __launch_bounds__(256) void gemm_kernel(
    const float* __restrict__ A, const float* __restrict__ Wm,
    const float* __restrict__ bias, float* __restrict__ C,
    const float* __restrict__ gate, int gateStride,
    int M, int Nc, int K,
    long long lda, long long ldbn, long long ldbk, long long ldc,
    int zdiv,
    long long as1, long long as2, long long bs1, long long bs2,
    long long cs1, long long cs2,
    int act)
{
    __shared__ float As[8][129];
    __shared__ float Bs[8][129];

    int z  = blockIdx.z;
    long long bq = z / zdiv, rq = z % zdiv;
    const float* Ab = A  + bq * as1 + rq * as2;
    const float* Wb = Wm + bq * bs1 + rq * bs2;
    float*       Cb = C  + bq * cs1 + rq * cs2;

    int m0 = blockIdx.y * 128;
    int n0 = blockIdx.x * 128;
    int t  = threadIdx.x;
    int tx = t & 15, ty = t >> 4;

    float acc[8][8];
    #pragma unroll
    for (int i = 0; i < 8; i++)
        #pragma unroll
        for (int j = 0; j < 8; j++) acc[i][j] = 0.f;

    for (int k0 = 0; k0 < K; k0 += 8) {
        #pragma unroll
        for (int s = 0; s < 4; s++) {
            int idx = t + s * 256;
            int kk = idx & 7, mm = idx >> 3;
            int gm = m0 + mm, gk = k0 + kk;
            As[kk][mm] = (gm < M && gk < K) ? Ab[(long long)gm * lda + gk] : 0.f;
            int gn = n0 + mm;
            Bs[kk][mm] = (gn < Nc && gk < K)
                       ? Wb[(long long)gn * ldbn + (long long)gk * ldbk] : 0.f;
        }
        __syncthreads();
        #pragma unroll
        for (int kk = 0; kk < 8; kk++) {
            float a[8], b[8];
            #pragma unroll
            for (int i = 0; i < 8; i++) a[i] = As[kk][ty + 16 * i];
            #pragma unroll
            for (int j = 0; j < 8; j++) b[j] = Bs[kk][tx + 16 * j];
            #pragma unroll
            for (int i = 0; i < 8; i++)
                #pragma unroll
                for (int j = 0; j < 8; j++) acc[i][j] += a[i] * b[j];
        }
        __syncthreads();
    }

    #pragma unroll
    for (int i = 0; i < 8; i++) {
        int row = m0 + ty + 16 * i;
        if (row >= M) continue;
        int bidx = row >> 10;
        #pragma unroll
        for (int j = 0; j < 8; j++) {
            int col = n0 + tx + 16 * j;
            if (col >= Nc) continue;
            float v = acc[i][j] + (bias ? bias[col] : 0.f);
            long long ci = (long long)row * ldc + col;
            if (gate) {
                Cb[ci] += gate[bidx * gateStride + col] * v;
            } else {
                if (act == 1) v = v / (1.f + expf(-v));   // silu
                Cb[ci] = v;
            }
        }
    }
}

// ---------------- timestep embedding ----------------
__global__ void temb_kernel(const float* __restrict__ t, float* __restrict__ temb)
{
    int b = blockIdx.x, i = threadIdx.x;          // i in [0,256)
    float tv = t[b];
    int d = i & 127;
    float fr = expf(-logf(10000.f) * (float)d / 128.f);
    float a = tv * fr;
    temb[b * 256 + i] = (i < 128) ? cosf(a) : sinf(a);
}

// ---------------- patch embed + pos embed ----------------
__global__ void patch_kernel(const float* __restrict__ x,
                             const float* __restrict__ pw,
                             const float* __restrict__ pb,
                             float* __restrict__ h)
{
    int row = blockIdx.x;              // b*1024 + n
    int b = row >> 10, n = row & 1023;
    int hp = n >> 4, wp = n & 15;
    int t = threadIdx.x;

    __shared__ float xs[32];
    if (t < 32) {
        int c = t >> 4, p = (t >> 2) & 3, q = t & 3;
        xs[t] = x[((long long)(b * 2 + c) * 256 + hp * 4 + p) * 64 + wp * 4 + q];
    }
    __syncthreads();

    #pragma unroll
    for (int i = 0; i < 4; i++) {
        int o = t + 256 * i;
        float acc = pb[o];
        #pragma unroll
        for (int j = 0; j < 32; j++) acc += xs[j] * pw[o * 32 + j];
        int r = o >> 8, dd = o & 255;
        float omega = expf(-(float)dd * (logf(10000.f) / 256.f));
        float pos = (r < 2) ? (float)wp : (float)hp;
        float ang = pos * omega;
        acc += (r & 1) ? cosf(ang) : sinf(ang);
        h[(long long)row * 1024 + o] = acc;
    }
}

// ---------------- rmsnorm + modulate ----------------
__global__ void rmsmod_kernel(const float* __restrict__ H, float* __restrict__ Hn,
                              const float* __restrict__ nw,
                              const float* __restrict__ shiftB,
                              const float* __restrict__ scaleB, int adaStride)
{
    int row = blockIdx.x;
    int b = row >> 10;
    int t = threadIdx.x;
    const float* xr = H + (long long)row * 1024;
    float v0 = xr[t], v1 = xr[t + 256], v2 = xr[t + 512], v3 = xr[t + 768];
    float ss = v0 * v0 + v1 * v1 + v2 * v2 + v3 * v3;

    __shared__ float sh[256];
    sh[t] = ss; __syncthreads();
    for (int o = 128; o > 0; o >>= 1) { if (t < o) sh[t] += sh[t + o]; __syncthreads(); }
    float rinv = rsqrtf(sh[0] * (1.f / 1024.f) + kEPS);

    const float* shv = shiftB + (long long)b * adaStride;
    const float* scv = scaleB + (long long)b * adaStride;
    float* y = Hn + (long long)row * 1024;
    y[t]       = v0 * rinv * nw[t]       * (1.f + scv[t])       + shv[t];
    y[t + 256] = v1 * rinv * nw[t + 256] * (1.f + scv[t + 256]) + shv[t + 256];
    y[t + 512] = v2 * rinv * nw[t + 512] * (1.f + scv[t + 512]) + shv[t + 512];
    y[t + 768] = v3 * rinv * nw[t + 768] * (1.f + scv[t + 768]) + shv[t + 768];
}

// ---------------- per-head q/k rmsnorm + rope (one warp per head-row) -------
__global__ void qkrope_kernel(float* __restrict__ qkv,
                              const float* __restrict__ qn,
                              const float* __restrict__ kn)
{
    int task = blockIdx.x * 8 + (threadIdx.x >> 5);   // 262144 tasks
    int lane = threadIdx.x & 31;
    int token = task >> 5;
    int r = task & 31;
    int which = r >> 4;        // 0=q 1=k
    int head  = r & 15;

    float* p = qkv + (long long)token * 3072 + which * 1024 + head * 64 + 2 * lane;
    float e0 = p[0], e1 = p[1];
    float ss = e0 * e0 + e1 * e1;
    #pragma unroll
    for (int o = 16; o > 0; o >>= 1) ss += __shfl_xor_sync(0xffffffffu, ss, o);
    float rinv = rsqrtf(ss * (1.f / 64.f) + kEPS);

    const float* w = which ? kn : qn;
    float n0 = e0 * rinv * w[2 * lane];
    float n1 = e1 * rinv * w[2 * lane + 1];

    int n = token & 1023;
    int hp = n >> 4, wp = n & 15;
    float pos = (lane < 16) ? (float)hp : (float)wp;
    float fr = expf(-(float)(lane & 15) * (logf(10000.f) / 16.f));
    float ang = pos * fr;
    float c = cosf(ang), s = sinf(ang);
    p[0] = n0 * c - n1 * s;
    p[1] = n1 * c + n0 * s;
}

// ---------------- row softmax with 1/sqrt(HD) scale ----------------
__global__ void softmax_kernel(float* __restrict__ S)
{
    long long row = blockIdx.x;
    float* p = S + row * 1024;
    int t = threadIdx.x;
    float v0 = p[t] * 0.125f, v1 = p[t + 256] * 0.125f,
          v2 = p[t + 512] * 0.125f, v3 = p[t + 768] * 0.125f;
    float mx = fmaxf(fmaxf(v0, v1), fmaxf(v2, v3));

    __shared__ float sh[256];
    sh[t] = mx; __syncthreads();
    for (int o = 128; o > 0; o >>= 1) { if (t < o) sh[t] = fmaxf(sh[t], sh[t + o]); __syncthreads(); }
    mx = sh[0]; __syncthreads();

    float e0 = expf(v0 - mx), e1 = expf(v1 - mx), e2 = expf(v2 - mx), e3 = expf(v3 - mx);
    sh[t] = e0 + e1 + e2 + e3; __syncthreads();
    for (int o = 128; o > 0; o >>= 1) { if (t < o) sh[t] += sh[t + o]; __syncthreads(); }
    float inv = 1.f / sh[0];
    p[t] = e0 * inv; p[t + 256] = e1 * inv; p[t + 512] = e2 * inv; p[t + 768] = e3 * inv;
}

// ---------------- swiglu ----------------
__global__ void swiglu_kernel(const float* __restrict__ x12, float* __restrict__ g)
{
    int row = blockIdx.y;
    int j = blockIdx.x * 256 + threadIdx.x;
    if (j >= kFFN) return;
    float a  = x12[(long long)row * 5460 + j];
    float b2 = x12[(long long)row * 5460 + kFFN + j];
    g[(long long)row * kFFN + j] = (a / (1.f + expf(-a))) * b2;
}

// ---------------- unpatchify ----------------
__global__ void unpatch_kernel(const float* __restrict__ y, float* __restrict__ out)
{
    int idx = blockIdx.x * 256 + threadIdx.x;      // < 262144
    int ww = idx & 63;
    int hh = (idx >> 6) & 255;
    int c  = (idx >> 14) & 1;
    int b  = idx >> 15;
    int hp = hh >> 2, p = hh & 3, wp = ww >> 2, q = ww & 3;
    out[idx] = y[((long long)(b * 1024 + hp * 16 + wp)) * 32 + (p * 4 + q) * 2 + c];
}

// ---------------- host-side gemm helper ----------------
static void gemm(const float* A, const float* Wm, const float* bias, float* C,
                 int M, int Nc, int K,
                 long long lda, long long ldbn, long long ldbk, long long ldc,
                 int batches = 1, int zdiv = 1,
                 long long as1 = 0, long long as2 = 0,
                 long long bs1 = 0, long long bs2 = 0,
                 long long cs1 = 0, long long cs2 = 0,
                 const float* gate = nullptr, int gateStride = 0, int act = 0)
{
    dim3 grid((Nc + 127) / 128, (M + 127) / 128, batches);
    gemm_kernel<<<grid, 256>>>(A, Wm, bias, C, gate, gateStride,
                               M, Nc, K, lda, ldbn, ldbk, ldc,
                               zdiv, as1, as2, bs1, bs2, cs1, cs2, act);
}

// ---------------- driver ----------------
extern "C" void kernel_launch(void* const* d_in, const int* /*in_sizes*/, int /*n_in*/,
                              void* d_out, int /*out_size*/)
{
    const float* x       = (const float*)d_in[0];
    const float* t       = (const float*)d_in[1];
    const float* patch_w = (const float*)d_in[2];
    const float* patch_b = (const float*)d_in[3];
    const float* t_w     = (const float*)d_in[4];
    const float* t_b     = (const float*)d_in[5];
    const float* norm1_w = (const float*)d_in[6];
    const float* qkv_w   = (const float*)d_in[7];
    const float* qkv_b   = (const float*)d_in[8];
    const float* qn_w    = (const float*)d_in[9];
    const float* kn_w    = (const float*)d_in[10];
    const float* proj_w  = (const float*)d_in[11];
    const float* proj_b  = (const float*)d_in[12];
    const float* norm2_w = (const float*)d_in[13];
    const float* w12_w   = (const float*)d_in[14];
    const float* w12_b   = (const float*)d_in[15];
    const float* w3_w    = (const float*)d_in[16];
    const float* w3_b    = (const float*)d_in[17];
    const float* ada_w   = (const float*)d_in[18];
    const float* ada_b   = (const float*)d_in[19];
    const float* fnorm_w = (const float*)d_in[20];
    const float* flin_w  = (const float*)d_in[21];
    const float* flin_b  = (const float*)d_in[22];
    const float* fada_w  = (const float*)d_in[23];
    const float* fada_b  = (const float*)d_in[24];
    float* out = (float*)d_out;

    float* base = nullptr;
    cudaGetSymbolAddress((void**)&base, g_scratch);
    float* temb = base + OFF_TEMB;
    float* cs   = base + OFF_CS;
    float* ada  = base + OFF_ADA;
    float* fada = base + OFF_FADA;
    float* h    = base + OFF_H;
    float* hn   = base + OFF_HN;
    float* qkv  = base + OFF_QKV;
    float* o    = base + OFF_O;
    float* x12  = base + OFF_X12;
    float* g    = base + OFF_G;
    float* y    = base + OFF_Y;
    float* sc   = base + OFF_SC;

    // conditioning
    temb_kernel<<<8, 256>>>(t, temb);
    gemm(temb, t_w, t_b, cs, 8, 1024, 256, 256, 256, 1, 1024,
         1, 1, 0, 0, 0, 0, 0, 0, nullptr, 0, /*act=silu*/1);

    // patch embed + pos embed
    patch_kernel<<<8192, 256>>>(x, patch_w, patch_b, h);

    for (int d = 0; d < 8; d++) {
        const float* adw = ada_w + (size_t)d * 6144 * 1024;
        // ada = cs @ ada_w^T + ada_b
        gemm(cs, adw, ada_b + d * 6144, ada, 8, 6144, 1024, 1024, 1024, 1, 6144);

        // hn = modulate(rmsnorm(h, norm1), sm, scm)
        rmsmod_kernel<<<8192, 256>>>(h, hn, norm1_w + d * 1024, ada, ada + 1024, 6144);

        // qkv
        gemm(hn, qkv_w + (size_t)d * 3072 * 1024, qkv_b + d * 3072, qkv,
             8192, 3072, 1024, 1024, 1024, 1, 3072);

        // per-head rmsnorm + rope on q,k
        qkrope_kernel<<<32768, 256>>>(qkv, qn_w + d * 64, kn_w + d * 64);

        // scores = Q @ K^T   (batched over 128 (b,head))
        gemm(qkv, qkv + 1024, nullptr, sc,
             1024, 1024, 64, 3072, 3072, 1, 1024,
             128, 16,
             1024LL * 3072, 64, 1024LL * 3072, 64,
             16LL << 20, 1LL << 20);

        softmax_kernel<<<131072, 256>>>(sc);

        // o = P @ V
        gemm(sc, qkv + 2048, nullptr, o,
             1024, 64, 1024, 1024, 1, 3072, 1024,
             128, 16,
             16LL << 20, 1LL << 20,
             1024LL * 3072, 64,
             1024LL * 1024, 64);

        // h += gm * (o @ proj^T + proj_b)
        gemm(o, proj_w + (size_t)d * 1024 * 1024, proj_b + d * 1024, h,
             8192, 1024, 1024, 1024, 1024, 1, 1024,
             1, 1, 0, 0, 0, 0, 0, 0, ada + 2048, 6144);

        // hn = modulate(rmsnorm(h, norm2), sp, scp)
        rmsmod_kernel<<<8192, 256>>>(h, hn, norm2_w + d * 1024, ada + 3072, ada + 4096, 6144);

        // x12 = hn @ w12^T + b
        gemm(hn, w12_w + (size_t)d * 5460 * 1024, w12_b + d * 5460, x12,
             8192, 5460, 1024, 1024, 1024, 1, 5460);

        // g = silu(x1) * x2
        swiglu_kernel<<<dim3(11, 8192), 256>>>(x12, g);

        // h += gp * (g @ w3^T + b)
        gemm(g, w3_w + (size_t)d * 1024 * 2730, w3_b + d * 1024, h,
             8192, 1024, 2730, 2730, 2730, 1, 1024,
             1, 1, 0, 0, 0, 0, 0, 0, ada + 5120, 6144);
    }

    // final adaLN + linear + unpatchify
    gemm(cs, fada_w, fada_b, fada, 8, 2048, 1024, 1024, 1024, 1, 2048);
    rmsmod_kernel<<<8192, 256>>>(h, hn, fnorm_w, fada, fada + 1024, 2048);
    gemm(hn, flin_w, flin_b, y, 8192, 32, 1024, 1024, 1024, 1, 32);
    unpatch_kernel<<<1024, 256>>>(y, out);
}